// round 15
// baseline (speedup 1.0000x reference)
#include <cuda_runtime.h>
#include <cuda_fp16.h>
#include <cstdint>

// ---------------------------------------------------------------------------
// GPe masked GEMM: out[b,u] = sum_i inputs[b,i]*(w[i,u]*mask[u,i]) + bias[u]
// compute_103 (no 'a') -> legacy mma.sync.m16n8k16 fp16/f32acc path.
// R15: R14 (half-stage mbarrier ring + split-K tail) with the two critical-
// path mbarrier waits moved INTO the ks pipeline (FULLH1 hidden under phase-3
// LDSM latency, next-iter FULLH0 hidden under phase-7 LDSM latency), and
// evict-first (.cs) output stores.
// ---------------------------------------------------------------------------

#define DB 16384
#define DK 3072
#define DN 3072
#define BM 128
#define BN 256
#define BK 128
#define NKI (DK / BK)          /* 24 */
#define ROWB 256                              /* bytes per smem row (128 fp16) */
#define A_STAGE_BYTES (BM * ROWB)             /* 32768 */
#define B_STAGE_BYTES (BN * ROWB)             /* 65536 */
#define STAGE_BYTES (A_STAGE_BYTES + B_STAGE_BYTES)  /* 98304 */
#define SMEM_BYTES (2 * STAGE_BYTES)                 /* 196608 */

#define W_SCALE 16384.0f
#define W_INV   (1.0f / 16384.0f)

#define N_TILES 1536           /* 12 x 128 */
#define FULL_TILES 1480        /* 10 full waves of 148 */
#define TAIL_TILES (N_TILES - FULL_TILES)   /* 56 */
#define GRID_GEMM (FULL_TILES + 2 * TAIL_TILES)  /* 1592 */

#define PW_BLOCKS (96 * 96)    /* 9216 prep_w tiles */
#define PA_BLOCKS 4096
#define PZ_BLOCKS TAIL_TILES   /* 56 zeroing blocks */

__device__ __align__(128) __half g_Ah[(size_t)DB * DK];  // fp16 inputs
__device__ __align__(128) __half g_Wh[(size_t)DN * DK];  // fp16 (w*mask*2^14)^T, [N,K]

// ------------------------------- helpers -----------------------------------

__device__ __forceinline__ void cp16(uint32_t d, const void* s) {
    asm volatile("cp.async.cg.shared.global [%0], [%1], 16;" :: "r"(d), "l"(s) : "memory");
}
__device__ __forceinline__ void cp_mbar_arrive_noinc(uint32_t a) {
    asm volatile("cp.async.mbarrier.arrive.noinc.shared.b64 [%0];" :: "r"(a) : "memory");
}
__device__ __forceinline__ void mbar_init(uint32_t a, uint32_t cnt) {
    asm volatile("mbarrier.init.shared.b64 [%0], %1;" :: "r"(a), "r"(cnt) : "memory");
}
__device__ __forceinline__ void mbar_arrive(uint32_t a) {
    asm volatile("mbarrier.arrive.shared.b64 _, [%0];" :: "r"(a) : "memory");
}
__device__ __forceinline__ void mbar_wait(uint32_t a, uint32_t ph) {
    uint32_t done;
    asm volatile("{ .reg .pred p; mbarrier.try_wait.parity.acquire.cta.shared::cta.b64 p, [%1], %2; selp.b32 %0,1,0,p; }"
                 : "=r"(done) : "r"(a), "r"(ph) : "memory");
    if (!done) {
        asm volatile("{ .reg .pred P1; WL%=: mbarrier.try_wait.parity.acquire.cta.shared::cta.b64 P1, [%0], %1, 0x989680; @P1 bra.uni WD%=; bra.uni WL%=; WD%=: }"
                     :: "r"(a), "r"(ph) : "memory");
    }
}

__device__ __forceinline__ void ldsm4(uint32_t& r0, uint32_t& r1, uint32_t& r2, uint32_t& r3,
                                      uint32_t addr) {
    asm volatile("ldmatrix.sync.aligned.m8n8.x4.shared.b16 {%0,%1,%2,%3}, [%4];"
                 : "=r"(r0), "=r"(r1), "=r"(r2), "=r"(r3) : "r"(addr));
}

__device__ __forceinline__ void mma_f16(float& d0, float& d1, float& d2, float& d3,
                                        uint32_t a0, uint32_t a1, uint32_t a2, uint32_t a3,
                                        uint32_t b0, uint32_t b1) {
    asm volatile("mma.sync.aligned.m16n8k16.row.col.f32.f16.f16.f32 "
                 "{%0,%1,%2,%3}, {%4,%5,%6,%7}, {%8,%9}, {%0,%1,%2,%3};"
                 : "+f"(d0), "+f"(d1), "+f"(d2), "+f"(d3)
                 : "r"(a0), "r"(a1), "r"(a2), "r"(a3), "r"(b0), "r"(b1));
}

__device__ __forceinline__ void stg_cs_v2(float* p, float x, float y) {
    asm volatile("st.global.cs.v2.f32 [%0], {%1,%2};" :: "l"(p), "f"(x), "f"(y) : "memory");
}

// --------------------------- prep kernel ------------------------------------
// Fused: [0, PW) w*mask transpose tiles; [PW, PW+PA) A fp32->fp16;
// [PW+PA, PW+PA+PZ) zero the split-K tail output tiles.
__global__ void prep_fused_kernel(const float* __restrict__ w,
                                  const int* __restrict__ mask,
                                  const float4* __restrict__ inA,
                                  float* __restrict__ out) {
    __shared__ float t[32][33];
    if (blockIdx.x < PW_BLOCKS) {
        const int k0 = (blockIdx.x % 96) * 32, n0 = (blockIdx.x / 96) * 32;
        const int tx = threadIdx.x & 31, ty = threadIdx.x >> 5;   // (32, 8)
#pragma unroll
        for (int j = 0; j < 4; ++j) {
            int k = k0 + ty + 8 * j;
            t[ty + 8 * j][tx] = w[(size_t)k * DN + n0 + tx];
        }
        __syncthreads();
#pragma unroll
        for (int j = 0; j < 4; ++j) {
            int n = n0 + ty + 8 * j;
            int k = k0 + tx;
            float v = t[tx][ty + 8 * j] * (float)mask[(size_t)n * DK + k] * W_SCALE;
            g_Wh[(size_t)n * DK + k] = __float2half_rn(v);
        }
    } else if (blockIdx.x < PW_BLOCKS + PA_BLOCKS) {
        size_t i = (size_t)(blockIdx.x - PW_BLOCKS) * blockDim.x + threadIdx.x;
        const size_t stride = (size_t)PA_BLOCKS * blockDim.x;
        uint2* o = reinterpret_cast<uint2*>(g_Ah);
        const size_t n4 = (size_t)DB * DK / 4;
        for (; i < n4; i += stride) {
            float4 v = __ldg(inA + i);
            __half2 h01 = __floats2half2_rn(v.x, v.y);
            __half2 h23 = __floats2half2_rn(v.z, v.w);
            uint2 u;
            u.x = *reinterpret_cast<uint32_t*>(&h01);
            u.y = *reinterpret_cast<uint32_t*>(&h23);
            o[i] = u;
        }
    } else {
        const int tileId = FULL_TILES + (int)(blockIdx.x - PW_BLOCKS - PA_BLOCKS);
        const int m0 = (tileId / 12) * BM;
        const int n0 = (tileId % 12) * BN;
        const float4 z = make_float4(0.f, 0.f, 0.f, 0.f);
        for (int idx = threadIdx.x; idx < BM * BN / 4; idx += blockDim.x) {
            int row = idx >> 6, col4 = idx & 63;
            *reinterpret_cast<float4*>(out + (size_t)(m0 + row) * DN + n0 + col4 * 4) = z;
        }
    }
}

// ------------------------------ GEMM ---------------------------------------
// 1D grid of 1592 CTAs: [0,1480) full tiles (24 k-iters), [1480,1592) pairs
// of half-K CTAs covering tiles 1480..1535 (12 k-iters, atomicAdd).
// Half-stage mbarrier ring; FULLH1 wait hidden at phase 3, next-iter FULLH0
// wait hidden at phase 7 (both under that phase's B-LDSM latency).

__global__ void __launch_bounds__(256, 1) gemm_f16(const float* __restrict__ bias,
                                                   float* __restrict__ out) {
    extern __shared__ char smem[];
    __shared__ __align__(8) uint64_t mbars[8];

    const int tid = threadIdx.x;
    const int wid = tid >> 5;
    const int lane = tid & 31;
    const int gid = lane >> 2;
    const int tg = lane & 3;
    const int warp_m = wid & 1;
    const int warp_n = wid >> 1;
    const bool half0prod = (wid < 4);

    // ---- tile decode -------------------------------------------------------
    int tileId, iters, kbase, khalf;
    {
        const int bid = (int)blockIdx.x;
        if (bid < FULL_TILES) {
            tileId = bid; khalf = -1; iters = NKI; kbase = 0;
        } else {
            const int tt = bid - FULL_TILES;
            tileId = FULL_TILES + (tt >> 1);
            khalf = tt & 1;
            iters = NKI / 2;
            kbase = khalf * (NKI / 2);
        }
    }
    const int m0 = (tileId / 12) * BM;
    const int n0 = (tileId % 12) * BN;

    const uint32_t smemBase = (uint32_t)__cvta_generic_to_shared(smem);
    const uint32_t mb = (uint32_t)__cvta_generic_to_shared(mbars);
#define FULLH0(s)  (mb + 8u * (s))
#define FULLH1(s)  (mb + 16u + 8u * (s))
#define EMPTYH0(s) (mb + 32u + 8u * (s))
#define EMPTYH1(s) (mb + 48u + 8u * (s))

    if (tid == 0) {
#pragma unroll
        for (int s = 0; s < 2; ++s) {
            mbar_init(FULLH0(s), 128);
            mbar_init(FULLH1(s), 128);
            mbar_init(EMPTYH0(s), 256);
            mbar_init(EMPTYH1(s), 256);
        }
    }
    __syncthreads();   // one-time: mbarrier init visibility

    // ---- cp.async mapping: warps 0-3 own chunks 0-7, warps 4-7 chunks 8-15 -
    const int r0 = (tid & 127) >> 3;
    const int cch = ((tid >> 7) << 3) + (tid & 7);    // 0..7 or 8..15
    const uint32_t key0 = (uint32_t)(r0 & 7);
    const uint32_t dstRow0 = (uint32_t)r0 * ROWB + (((uint32_t)cch ^ key0) << 4);
    const char* aSrc0 = (const char*)(g_Ah + (size_t)(m0 + r0) * DK + cch * 8)
                        + (size_t)kbase * (BK * 2);
    const char* bSrc0 = (const char*)(g_Wh + (size_t)(n0 + r0) * DK + cch * 8)
                        + (size_t)kbase * (BK * 2);
    const size_t srcRowStride = (size_t)16 * DK * 2;
    const uint32_t dstRowStride = 16 * ROWB;

    // ---- ldmatrix row bases ------------------------------------------------
    const int ac0 = lane >> 4;
    const int arow = warp_m * 64 + (lane & 15);
    const int bc0 = (lane >> 3) & 1;
    const int brow = warp_n * 64 + ((lane >> 4) << 3) + (lane & 7);

    uint32_t aBase[4], aKey[4], bBase[4], bKey[4];
#pragma unroll
    for (int mi = 0; mi < 4; ++mi) {
        int row = arow + mi * 16;
        aBase[mi] = (uint32_t)row * ROWB;
        aKey[mi] = (uint32_t)(row & 7);
    }
#pragma unroll
    for (int nj = 0; nj < 4; ++nj) {
        int row = brow + nj * 16;
        bBase[nj] = A_STAGE_BYTES + (uint32_t)row * ROWB;
        bKey[nj] = (uint32_t)(row & 7);
    }

    float acc[4][8][4];
#pragma unroll
    for (int mi = 0; mi < 4; ++mi)
#pragma unroll
        for (int ni = 0; ni < 8; ++ni)
#pragma unroll
            for (int q = 0; q < 4; ++q) acc[mi][ni][q] = 0.0f;

    // ---- prologue: fill stage 0 (each warp-group its own half) -------------
    {
        uint32_t st = smemBase;
#pragma unroll
        for (int j = 0; j < 8; ++j)
            cp16(st + dstRow0 + j * dstRowStride, aSrc0 + j * srcRowStride);
#pragma unroll
        for (int j = 0; j < 16; ++j)
            cp16(st + A_STAGE_BYTES + dstRow0 + j * dstRowStride, bSrc0 + j * srcRowStride);
        cp_mbar_arrive_noinc(half0prod ? FULLH0(0) : FULLH1(0));
    }

    mbar_wait(FULLH0(0), 0);   // steady-state FULLH0 waits happen at ks==7

    // ---- mainloop: half-stage mbarrier ring, hidden waits ------------------
    for (int it = 0; it < iters; ++it) {
        const uint32_t pf = (uint32_t)((it >> 1) & 1);
        const int s = it & 1;

        const int nf = it + 1;
        const bool doLoad = (nf < iters);
        const int sn = nf & 1;
        const uint32_t pe = (uint32_t)(((nf >> 1) - 1) & 1);
        const uint32_t pfN = (uint32_t)((nf >> 1) & 1);
        const uint32_t stNext = smemBase + sn * STAGE_BYTES;
        const size_t kofsNext = (size_t)nf * (BK * 2);
        const uint32_t stg = smemBase + s * STAGE_BYTES;

#pragma unroll
        for (int ks = 0; ks < 8; ++ks) {
            // ---- producer side (warp-uniform branch) -----------------------
            if (doLoad) {
                if (half0prod) {
                    if (ks == 1 && nf > 1) mbar_wait(EMPTYH0(sn), pe);
                    if (ks >= 1 && ks <= 4) {
                        const int p = ks - 1;
                        cp16(stNext + dstRow0 + (2 * p) * dstRowStride,
                             aSrc0 + (2 * p) * srcRowStride + kofsNext);
                        cp16(stNext + dstRow0 + (2 * p + 1) * dstRowStride,
                             aSrc0 + (2 * p + 1) * srcRowStride + kofsNext);
#pragma unroll
                        for (int q = 0; q < 4; ++q)
                            cp16(stNext + A_STAGE_BYTES + dstRow0 + (4 * p + q) * dstRowStride,
                                 bSrc0 + (4 * p + q) * srcRowStride + kofsNext);
                        if (ks == 4) cp_mbar_arrive_noinc(FULLH0(sn));
                    }
                } else {
                    if (ks == 3 && nf > 1) mbar_wait(EMPTYH1(sn), pe);
                    if (ks >= 3 && ks <= 6) {
                        const int p = ks - 3;
                        cp16(stNext + dstRow0 + (2 * p) * dstRowStride,
                             aSrc0 + (2 * p) * srcRowStride + kofsNext);
                        cp16(stNext + dstRow0 + (2 * p + 1) * dstRowStride,
                             aSrc0 + (2 * p + 1) * srcRowStride + kofsNext);
#pragma unroll
                        for (int q = 0; q < 4; ++q)
                            cp16(stNext + A_STAGE_BYTES + dstRow0 + (4 * p + q) * dstRowStride,
                                 bSrc0 + (4 * p + q) * srcRowStride + kofsNext);
                        if (ks == 6) cp_mbar_arrive_noinc(FULLH1(sn));
                    }
                }
            }

            // ---- B fragments for this phase --------------------------------
            uint32_t bf[4][4];
#pragma unroll
            for (int nj = 0; nj < 4; ++nj)
                ldsm4(bf[nj][0], bf[nj][1], bf[nj][2], bf[nj][3],
                      stg + bBase[nj] + ((((uint32_t)(bc0 + 2 * ks)) ^ bKey[nj]) << 4));

            // ---- hidden waits: overlap with the B-LDSM latency above -------
            // phase 3 touches only half0 -> safe to wait FULLH1 here (needed
            // from phase 4); phase 7 touches only half1 -> safe to wait next
            // iteration's FULLH0 here.
            if (ks == 3) mbar_wait(FULLH1(s), pf);
            if (ks == 7 && doLoad) mbar_wait(FULLH0(sn), pfN);

            // ---- A fragments + MMA burst -----------------------------------
#pragma unroll
            for (int mi = 0; mi < 4; ++mi) {
                uint32_t a0, a1, a2, a3;
                ldsm4(a0, a1, a2, a3,
                      stg + aBase[mi] + ((((uint32_t)(ac0 + 2 * ks)) ^ aKey[mi]) << 4));
#pragma unroll
                for (int nj = 0; nj < 4; ++nj) {
                    mma_f16(acc[mi][2 * nj][0], acc[mi][2 * nj][1],
                            acc[mi][2 * nj][2], acc[mi][2 * nj][3],
                            a0, a1, a2, a3, bf[nj][0], bf[nj][1]);
                    mma_f16(acc[mi][2 * nj + 1][0], acc[mi][2 * nj + 1][1],
                            acc[mi][2 * nj + 1][2], acc[mi][2 * nj + 1][3],
                            a0, a1, a2, a3, bf[nj][2], bf[nj][3]);
                }
            }
            if (ks == 3) mbar_arrive(EMPTYH0(s));   // last half0 use was phase 3
        }
        mbar_arrive(EMPTYH1(s));    // done with half1 (and the stage)
    }

    // ---- epilogue ----------------------------------------------------------
    if (khalf < 0) {
        // full tile: scale + bias, evict-first .cs stores (write-once data)
#pragma unroll
        for (int mi = 0; mi < 4; ++mi) {
            const int row0 = m0 + warp_m * 64 + mi * 16 + gid;
#pragma unroll
            for (int ni = 0; ni < 8; ++ni) {
                const int col = n0 + warp_n * 64 + ni * 8 + 2 * tg;
                const float2 bb = *reinterpret_cast<const float2*>(bias + col);
                stg_cs_v2(out + (size_t)row0 * DN + col,
                          acc[mi][ni][0] * W_INV + bb.x,
                          acc[mi][ni][1] * W_INV + bb.y);
                stg_cs_v2(out + (size_t)(row0 + 8) * DN + col,
                          acc[mi][ni][2] * W_INV + bb.x,
                          acc[mi][ni][3] * W_INV + bb.y);
            }
        }
    } else {
        // split-K half: atomicAdd partial (bias by half 0 only); pre-zeroed;
        // exactly 2 adds per element -> deterministic
        const float addB = (khalf == 0) ? 1.0f : 0.0f;
#pragma unroll
        for (int mi = 0; mi < 4; ++mi) {
            const int row0 = m0 + warp_m * 64 + mi * 16 + gid;
#pragma unroll
            for (int ni = 0; ni < 8; ++ni) {
                const int col = n0 + warp_n * 64 + ni * 8 + 2 * tg;
                const float2 bb = *reinterpret_cast<const float2*>(bias + col);
                atomicAdd(out + (size_t)row0 * DN + col,
                          acc[mi][ni][0] * W_INV + addB * bb.x);
                atomicAdd(out + (size_t)row0 * DN + col + 1,
                          acc[mi][ni][1] * W_INV + addB * bb.y);
                atomicAdd(out + (size_t)(row0 + 8) * DN + col,
                          acc[mi][ni][2] * W_INV + addB * bb.x);
                atomicAdd(out + (size_t)(row0 + 8) * DN + col + 1,
                          acc[mi][ni][3] * W_INV + addB * bb.y);
            }
        }
    }
#undef FULLH0
#undef FULLH1
#undef EMPTYH0
#undef EMPTYH1
}

// ------------------------------ launch -------------------------------------

extern "C" void kernel_launch(void* const* d_in, const int* in_sizes, int n_in,
                              void* d_out, int out_size) {
    (void)in_sizes; (void)n_in; (void)out_size;
    const float* inp  = (const float*)d_in[0];
    const float* w    = (const float*)d_in[1];
    const float* bias = (const float*)d_in[2];
    const int*   mask = (const int*)d_in[3];
    float* out = (float*)d_out;

    static bool attr_set = false;
    if (!attr_set) {
        cudaFuncSetAttribute(gemm_f16, cudaFuncAttributeMaxDynamicSharedMemorySize, SMEM_BYTES);
        attr_set = true;
    }

    prep_fused_kernel<<<PW_BLOCKS + PA_BLOCKS + PZ_BLOCKS, 256>>>(
        w, mask, (const float4*)inp, out);
    gemm_f16<<<GRID_GEMM, 256, SMEM_BYTES>>>(bias, out);
}